// round 5
// baseline (speedup 1.0000x reference)
#include <cuda_runtime.h>
#include <stdint.h>

#define BATCH 4
#define SEQ   2048
#define DIM   1024
#define NH    16
#define HD    64
#define SCALE 0.125f
#define MTOT  (BATCH*SEQ)

// ---- scratch ----
__device__ float g_q[MTOT * DIM];
__device__ float g_k[MTOT * DIM];
__device__ float g_v[MTOT * DIM];
__device__ float g_ctx[MTOT * DIM];
__device__ float g_r[(size_t)BATCH * SEQ * SEQ];  // 1/Z
__device__ float g_x[MTOT * DIM];                 // tf32-rounded x
__device__ float g_w[4 * DIM * DIM];              // tf32-rounded weights

// ---- helpers ----
__device__ __forceinline__ uint32_t f2tf(float x) {
    uint32_t u;
    asm("cvt.rna.tf32.f32 %0, %1;" : "=r"(u) : "f"(x));
    return u;
}
__device__ __forceinline__ uint32_t ldbits(const float* p) { return __float_as_uint(*p); }

__device__ __forceinline__ void mma8(float c[4], const uint32_t a[4], const uint32_t b[2]) {
    asm volatile(
        "mma.sync.aligned.m16n8k8.row.col.f32.tf32.tf32.f32 "
        "{%0,%1,%2,%3}, {%4,%5,%6,%7}, {%8,%9}, {%0,%1,%2,%3};\n"
        : "+f"(c[0]), "+f"(c[1]), "+f"(c[2]), "+f"(c[3])
        : "r"(a[0]), "r"(a[1]), "r"(a[2]), "r"(a[3]), "r"(b[0]), "r"(b[1]));
}
__device__ __forceinline__ void cpa16(float* s, const float* g) {
    uint32_t sa = (uint32_t)__cvta_generic_to_shared(s);
    asm volatile("cp.async.ca.shared.global [%0], [%1], 16;\n" ::"r"(sa), "l"(g));
}
__device__ __forceinline__ void cp_commit() { asm volatile("cp.async.commit_group;\n"); }
template <int N>
__device__ __forceinline__ void cp_wait() { asm volatile("cp.async.wait_group %0;\n" ::"n"(N)); }

// =====================================================================
// Elementwise tf32 rounding. grid.y selects segment (for weights pack).
// =====================================================================
__global__ void round_tf32(const float* __restrict__ in, float* __restrict__ out, int n4) {
    int i = blockIdx.x * blockDim.x + threadIdx.x;
    int stride = gridDim.x * blockDim.x;
    for (; i < n4; i += stride) {
        float4 v = ((const float4*)in)[i];
        v.x = __uint_as_float(f2tf(v.x));
        v.y = __uint_as_float(f2tf(v.y));
        v.z = __uint_as_float(f2tf(v.z));
        v.w = __uint_as_float(f2tf(v.w));
        ((float4*)out)[i] = v;
    }
}

__global__ void round_tf32_w4(const float* __restrict__ w0, const float* __restrict__ w1,
                              const float* __restrict__ w2, const float* __restrict__ w3,
                              float* __restrict__ out) {
    const float* src = (blockIdx.y == 0) ? w0 : (blockIdx.y == 1) ? w1 : (blockIdx.y == 2) ? w2 : w3;
    float* dst = out + (size_t)blockIdx.y * DIM * DIM;
    const int n4 = DIM * DIM / 4;
    int i = blockIdx.x * blockDim.x + threadIdx.x;
    int stride = gridDim.x * blockDim.x;
    for (; i < n4; i += stride) {
        float4 v = ((const float4*)src)[i];
        v.x = __uint_as_float(f2tf(v.x));
        v.y = __uint_as_float(f2tf(v.y));
        v.z = __uint_as_float(f2tf(v.z));
        v.w = __uint_as_float(f2tf(v.w));
        ((float4*)dst)[i] = v;
    }
}

// =====================================================================
// GEMM: C[M,1024] = A @ W.  Block 128x256x32, 8 warps (2m x 4n), warp 64x64.
// Inputs pre-rounded tf32. 4-stage cp.async pipeline.
// =====================================================================
#define GS 4
#define SA_ST (128 * 36)
#define SB_ST (32 * 264)
#define G_SMEM (GS * (SA_ST + SB_ST) * 4)

__global__ __launch_bounds__(256) void gemm_tf32(const float* __restrict__ A,
                                                 const float* __restrict__ W,
                                                 float* __restrict__ C, int cvt_store) {
    extern __shared__ float sm[];
    float* sA = sm;
    float* sB = sm + GS * SA_ST;
    const int tid = threadIdx.x;
    const int m0 = blockIdx.y * 128, n0 = blockIdx.x * 256;
    const int w = tid >> 5, lane = tid & 31, g = lane >> 2, tg = lane & 3;
    const int wm = (w >> 2) * 64, wn = (w & 3) * 64;

    float acc[4][8][4]{};

    auto load_tile = [&](int st, int kt) {
        float* a = sA + st * SA_ST;
        float* b = sB + st * SB_ST;
#pragma unroll
        for (int i = 0; i < 4; i++) {
            int c = tid + 256 * i;
            int r = c >> 3, cc = (c & 7) * 4;
            cpa16(a + r * 36 + cc, A + (size_t)(m0 + r) * DIM + kt + cc);
        }
#pragma unroll
        for (int i = 0; i < 8; i++) {
            int c = tid + 256 * i;
            int r = c >> 6, cc = (c & 63) * 4;
            cpa16(b + r * 264 + cc, W + (size_t)(kt + r) * DIM + n0 + cc);
        }
    };

    const int NK = DIM / 32;
#pragma unroll
    for (int s = 0; s < GS - 1; s++) {
        load_tile(s, s * 32);
        cp_commit();
    }
    for (int t = 0; t < NK; t++) {
        cp_wait<GS - 2>();
        __syncthreads();
        int ld = t + GS - 1;
        if (ld < NK) load_tile(ld % GS, ld * 32);
        cp_commit();
        const float* a = sA + (t % GS) * SA_ST;
        const float* b = sB + (t % GS) * SB_ST;
#pragma unroll
        for (int kk = 0; kk < 32; kk += 8) {
            uint32_t af[4][4], bf[8][2];
#pragma unroll
            for (int mt = 0; mt < 4; mt++) {
                int r = wm + mt * 16;
                af[mt][0] = ldbits(a + (r + g) * 36 + kk + tg);
                af[mt][1] = ldbits(a + (r + g + 8) * 36 + kk + tg);
                af[mt][2] = ldbits(a + (r + g) * 36 + kk + tg + 4);
                af[mt][3] = ldbits(a + (r + g + 8) * 36 + kk + tg + 4);
            }
#pragma unroll
            for (int nt = 0; nt < 8; nt++) {
                int nb = wn + nt * 8;
                bf[nt][0] = ldbits(b + (kk + tg) * 264 + nb + g);
                bf[nt][1] = ldbits(b + (kk + tg + 4) * 264 + nb + g);
            }
#pragma unroll
            for (int mt = 0; mt < 4; mt++)
#pragma unroll
                for (int nt = 0; nt < 8; nt++) mma8(acc[mt][nt], af[mt], bf[nt]);
        }
    }
#pragma unroll
    for (int mt = 0; mt < 4; mt++)
#pragma unroll
        for (int nt = 0; nt < 8; nt++) {
            int row = m0 + wm + mt * 16 + g;
            int col = n0 + wn + nt * 8 + 2 * tg;
            float e[4];
#pragma unroll
            for (int i = 0; i < 4; i++)
                e[i] = cvt_store ? __uint_as_float(f2tf(acc[mt][nt][i])) : acc[mt][nt][i];
            *(float2*)(C + (size_t)row * DIM + col) = make_float2(e[0], e[1]);
            *(float2*)(C + (size_t)(row + 8) * DIM + col) = make_float2(e[2], e[3]);
        }
}

// =====================================================================
// Pass A: R[b,q,k] = 1 / sum_h exp(scale * q_h . k_h)
// 128x128 tile, 8 warps (2m x 4n, 64x32), heads triple-buffered.
// =====================================================================
#define ZT_ST (128 * 68)
#define Z_SMEM (6 * ZT_ST * 4)

__global__ __launch_bounds__(256) void attn_z() {
    extern __shared__ float sm[];
    float* sQ = sm;              // [3][128*68]
    float* sK = sm + 3 * ZT_ST;  // [3][128*68]
    const int tid = threadIdx.x;
    const int b = blockIdx.z, qt = blockIdx.y * 128, kt = blockIdx.x * 128;
    const int w = tid >> 5, lane = tid & 31, g = lane >> 2, tg = lane & 3;
    const int wm = (w >> 2) * 64, wn = (w & 3) * 32;

    const float* qb = g_q + (size_t)(b * SEQ + qt) * DIM;
    const float* kb = g_k + (size_t)(b * SEQ + kt) * DIM;

    auto load_head = [&](int st, int h) {
        float* q = sQ + st * ZT_ST;
        float* k = sK + st * ZT_ST;
#pragma unroll
        for (int i = 0; i < 8; i++) {
            int c = tid + 256 * i;
            int r = c >> 4, cc = (c & 15) * 4;
            cpa16(q + r * 68 + cc, qb + (size_t)r * DIM + h * HD + cc);
            cpa16(k + r * 68 + cc, kb + (size_t)r * DIM + h * HD + cc);
        }
    };

    float zacc[4][4][4]{};
    load_head(0, 0);
    cp_commit();
    load_head(1, 1);
    cp_commit();

    int st = 0;
    for (int h = 0; h < NH; h++) {
        cp_wait<1>();
        __syncthreads();
        if (h + 2 < NH) load_head((st + 2) % 3, h + 2);
        cp_commit();
        const float* q = sQ + st * ZT_ST;
        const float* k = sK + st * ZT_ST;
        st = (st + 1) % 3;

        float sacc[4][4][4]{};
#pragma unroll
        for (int kk = 0; kk < 64; kk += 8) {
            uint32_t af[4][4], bf[4][2];
#pragma unroll
            for (int mt = 0; mt < 4; mt++) {
                int r = wm + mt * 16;
                af[mt][0] = ldbits(q + (r + g) * 68 + kk + tg);
                af[mt][1] = ldbits(q + (r + g + 8) * 68 + kk + tg);
                af[mt][2] = ldbits(q + (r + g) * 68 + kk + tg + 4);
                af[mt][3] = ldbits(q + (r + g + 8) * 68 + kk + tg + 4);
            }
#pragma unroll
            for (int nt = 0; nt < 4; nt++) {
                int nb = wn + nt * 8;
                bf[nt][0] = ldbits(k + (nb + g) * 68 + kk + tg);
                bf[nt][1] = ldbits(k + (nb + g) * 68 + kk + tg + 4);
            }
#pragma unroll
            for (int mt = 0; mt < 4; mt++)
#pragma unroll
                for (int nt = 0; nt < 4; nt++) mma8(sacc[mt][nt], af[mt], bf[nt]);
        }
#pragma unroll
        for (int i = 0; i < 4; i++)
#pragma unroll
            for (int j = 0; j < 4; j++)
#pragma unroll
                for (int e = 0; e < 4; e++) zacc[i][j][e] += __expf(sacc[i][j][e] * SCALE);
    }
#pragma unroll
    for (int mt = 0; mt < 4; mt++)
#pragma unroll
        for (int nt = 0; nt < 4; nt++) {
            int row = qt + wm + mt * 16 + g;
            int col = kt + wn + nt * 8 + 2 * tg;
            float* rp = g_r + ((size_t)b * SEQ + row) * SEQ + col;
            *(float2*)rp = make_float2(1.f / zacc[mt][nt][0], 1.f / zacc[mt][nt][1]);
            *(float2*)(rp + (size_t)8 * SEQ) = make_float2(1.f / zacc[mt][nt][2], 1.f / zacc[mt][nt][3]);
        }
}

// =====================================================================
// Pass B: ctx = sum_k exp(scale*S)*R * V  per (b,h,qtile).
// GEMM1: 8 warps 2m x 4n (64x32). GEMM2: 2m x 2n x 2ksplit (64x32).
// h = blockIdx.x so CTAs sharing R rows are launch-adjacent (L2 reuse).
// =====================================================================
#define CQ_ST (128 * 68)
#define CV_ST (128 * 72)
#define CP_ST (128 * 132)
#define C_SMEM ((3 * CQ_ST + CV_ST + CP_ST) * 4)

__global__ __launch_bounds__(256) void attn_ctx() {
    extern __shared__ float sm[];
    float* sQ = sm;
    float* sK = sm + CQ_ST;  // [2]
    float* sV = sm + 3 * CQ_ST;
    float* sP = sV + CV_ST;

    const int tid = threadIdx.x;
    const int b = blockIdx.z, h = blockIdx.x, qt = blockIdx.y * 128;
    const int w = tid >> 5, lane = tid & 31, g = lane >> 2, tg = lane & 3;
    const int wm = (w >> 2) * 64, wn = (w & 3) * 32;
    const int wk2 = (w >> 1) & 1, wn2 = (w & 1) * 32;  // GEMM2 k-split / n

    const float* qb = g_q + (size_t)(b * SEQ + qt) * DIM + h * HD;
#pragma unroll
    for (int i = 0; i < 8; i++) {
        int c = tid + 256 * i;
        int r = c >> 4, cc = (c & 15) * 4;
        cpa16(sQ + r * 68 + cc, qb + (size_t)r * DIM + cc);
    }
    {
        const float* kb = g_k + (size_t)(b * SEQ) * DIM + h * HD;
#pragma unroll
        for (int i = 0; i < 8; i++) {
            int c = tid + 256 * i;
            int r = c >> 4, cc = (c & 15) * 4;
            cpa16(sK + r * 68 + cc, kb + (size_t)r * DIM + cc);
        }
    }
    cp_commit();

    float cacc[4][4][4]{};

    for (int t = 0; t < SEQ / 128; t++) {
        const int kt = t * 128;
        {
            const float* vb = g_v + (size_t)(b * SEQ + kt) * DIM + h * HD;
#pragma unroll
            for (int i = 0; i < 8; i++) {
                int c = tid + 256 * i;
                int r = c >> 4, cc = (c & 15) * 4;
                cpa16(sV + r * 72 + cc, vb + (size_t)r * DIM + cc);
            }
            const float* rb = g_r + ((size_t)b * SEQ + qt) * SEQ + kt;
#pragma unroll
            for (int i = 0; i < 16; i++) {
                int c = tid + 256 * i;
                int r = c >> 5, cc = (c & 31) * 4;
                cpa16(sP + r * 132 + cc, rb + (size_t)r * SEQ + cc);
            }
        }
        cp_commit();
        cp_wait<1>();  // K(t) (and Q) ready
        __syncthreads();

        {
            int ktn = (t + 1 < SEQ / 128) ? kt + 128 : 0;
            const float* kb = g_k + (size_t)(b * SEQ + ktn) * DIM + h * HD;
            float* kd = sK + ((t + 1) & 1) * CQ_ST;
#pragma unroll
            for (int i = 0; i < 8; i++) {
                int c = tid + 256 * i;
                int r = c >> 4, cc = (c & 15) * 4;
                cpa16(kd + r * 68 + cc, kb + (size_t)r * DIM + cc);
            }
        }
        cp_commit();

        // GEMM1: S = Q @ K^T (128x128x64)
        const float* kc = sK + (t & 1) * CQ_ST;
        float sacc[4][4][4]{};
#pragma unroll
        for (int kk = 0; kk < 64; kk += 8) {
            uint32_t af[4][4], bf[4][2];
#pragma unroll
            for (int mt = 0; mt < 4; mt++) {
                int r = wm + mt * 16;
                af[mt][0] = ldbits(sQ + (r + g) * 68 + kk + tg);
                af[mt][1] = ldbits(sQ + (r + g + 8) * 68 + kk + tg);
                af[mt][2] = ldbits(sQ + (r + g) * 68 + kk + tg + 4);
                af[mt][3] = ldbits(sQ + (r + g + 8) * 68 + kk + tg + 4);
            }
#pragma unroll
            for (int nt = 0; nt < 4; nt++) {
                int nb = wn + nt * 8;
                bf[nt][0] = ldbits(kc + (nb + g) * 68 + kk + tg);
                bf[nt][1] = ldbits(kc + (nb + g) * 68 + kk + tg + 4);
            }
#pragma unroll
            for (int mt = 0; mt < 4; mt++)
#pragma unroll
                for (int nt = 0; nt < 4; nt++) mma8(sacc[mt][nt], af[mt], bf[nt]);
        }

        cp_wait<1>();  // V(t), R(t) ready
        __syncthreads();

        // P = tf32(exp(scale*S) * R), in-place in sP
#pragma unroll
        for (int mt = 0; mt < 4; mt++)
#pragma unroll
            for (int nt = 0; nt < 4; nt++) {
                int row = wm + mt * 16 + g;
                int col = wn + nt * 8 + 2 * tg;
                float2* p0 = (float2*)(sP + row * 132 + col);
                float2* p1 = (float2*)(sP + (row + 8) * 132 + col);
                float2 r0 = *p0, r1 = *p1;
                *p0 = make_float2(__uint_as_float(f2tf(__expf(sacc[mt][nt][0] * SCALE) * r0.x)),
                                  __uint_as_float(f2tf(__expf(sacc[mt][nt][1] * SCALE) * r0.y)));
                *p1 = make_float2(__uint_as_float(f2tf(__expf(sacc[mt][nt][2] * SCALE) * r1.x)),
                                  __uint_as_float(f2tf(__expf(sacc[mt][nt][3] * SCALE) * r1.y)));
            }
        __syncthreads();

        // GEMM2: ctx += P @ V  (128x64x128, k-split over warps)
#pragma unroll
        for (int kk = 0; kk < 64; kk += 8) {
            const int kx = wk2 * 64 + kk;
            uint32_t af[4][4], bf[4][2];
#pragma unroll
            for (int mt = 0; mt < 4; mt++) {
                int r = wm + mt * 16;
                af[mt][0] = ldbits(sP + (r + g) * 132 + kx + tg);
                af[mt][1] = ldbits(sP + (r + g + 8) * 132 + kx + tg);
                af[mt][2] = ldbits(sP + (r + g) * 132 + kx + tg + 4);
                af[mt][3] = ldbits(sP + (r + g + 8) * 132 + kx + tg + 4);
            }
#pragma unroll
            for (int nt = 0; nt < 4; nt++) {
                int nb = wn2 + nt * 8;
                bf[nt][0] = ldbits(sV + (kx + tg) * 72 + nb + g);
                bf[nt][1] = ldbits(sV + (kx + tg + 4) * 72 + nb + g);
            }
#pragma unroll
            for (int mt = 0; mt < 4; mt++)
#pragma unroll
                for (int nt = 0; nt < 4; nt++) mma8(cacc[mt][nt], af[mt], bf[nt]);
        }
        __syncthreads();
    }

    // reduce k-split partials via sP
    if (wk2 == 1) {
#pragma unroll
        for (int mt = 0; mt < 4; mt++)
#pragma unroll
            for (int nt = 0; nt < 4; nt++) {
                int row = wm + mt * 16 + g;
                int col = wn2 + nt * 8 + 2 * tg;
                *(float2*)(sP + row * 132 + col) = make_float2(cacc[mt][nt][0], cacc[mt][nt][1]);
                *(float2*)(sP + (row + 8) * 132 + col) = make_float2(cacc[mt][nt][2], cacc[mt][nt][3]);
            }
    }
    __syncthreads();
    if (wk2 == 0) {
        float* cb = g_ctx + (size_t)(b * SEQ + qt) * DIM + h * HD;
#pragma unroll
        for (int mt = 0; mt < 4; mt++)
#pragma unroll
            for (int nt = 0; nt < 4; nt++) {
                int row = wm + mt * 16 + g;
                int col = wn2 + nt * 8 + 2 * tg;
                float2 o0 = *(float2*)(sP + row * 132 + col);
                float2 o1 = *(float2*)(sP + (row + 8) * 132 + col);
                o0.x += cacc[mt][nt][0];
                o0.y += cacc[mt][nt][1];
                o1.x += cacc[mt][nt][2];
                o1.y += cacc[mt][nt][3];
                *(float2*)(cb + (size_t)row * DIM + col) =
                    make_float2(__uint_as_float(f2tf(o0.x)), __uint_as_float(f2tf(o0.y)));
                *(float2*)(cb + (size_t)(row + 8) * DIM + col) =
                    make_float2(__uint_as_float(f2tf(o1.x)), __uint_as_float(f2tf(o1.y)));
            }
    }
}

// =====================================================================
extern "C" void kernel_launch(void* const* d_in, const int* in_sizes, int n_in,
                              void* d_out, int out_size) {
    const float* x = (const float*)d_in[0];
    const float* wq = (const float*)d_in[1];
    const float* wk = (const float*)d_in[2];
    const float* wv = (const float*)d_in[3];
    const float* wo = (const float*)d_in[4];
    float* out = (float*)d_out;

    float *q, *k, *v, *ctx, *xr, *wr;
    cudaGetSymbolAddress((void**)&q, g_q);
    cudaGetSymbolAddress((void**)&k, g_k);
    cudaGetSymbolAddress((void**)&v, g_v);
    cudaGetSymbolAddress((void**)&ctx, g_ctx);
    cudaGetSymbolAddress((void**)&xr, g_x);
    cudaGetSymbolAddress((void**)&wr, g_w);

    static int attr_done = 0;
    if (!attr_done) {
        cudaFuncSetAttribute(gemm_tf32, cudaFuncAttributeMaxDynamicSharedMemorySize, G_SMEM);
        cudaFuncSetAttribute(attn_z, cudaFuncAttributeMaxDynamicSharedMemorySize, Z_SMEM);
        cudaFuncSetAttribute(attn_ctx, cudaFuncAttributeMaxDynamicSharedMemorySize, C_SMEM);
        attr_done = 1;
    }

    round_tf32<<<2048, 256>>>(x, xr, MTOT * DIM / 4);
    round_tf32_w4<<<dim3(256, 4), 256>>>(wq, wk, wv, wo, wr);

    dim3 gg(DIM / 256, MTOT / 128);  // (4, 64)
    gemm_tf32<<<gg, 256, G_SMEM>>>(xr, wr + 0 * DIM * DIM, q, 1);
    gemm_tf32<<<gg, 256, G_SMEM>>>(xr, wr + 1 * DIM * DIM, k, 1);
    gemm_tf32<<<gg, 256, G_SMEM>>>(xr, wr + 2 * DIM * DIM, v, 1);

    attn_z<<<dim3(SEQ / 128, SEQ / 128, BATCH), 256, Z_SMEM>>>();

    attn_ctx<<<dim3(NH, SEQ / 128, BATCH), 256, C_SMEM>>>();

    gemm_tf32<<<gg, 256, G_SMEM>>>(ctx, wr + 3 * DIM * DIM, out, 0);
}

// round 6
// speedup vs baseline: 1.0251x; 1.0251x over previous
#include <cuda_runtime.h>
#include <stdint.h>

#define BATCH 4
#define SEQ   2048
#define DIM   1024
#define NH    16
#define HD    64
#define SCALE 0.125f
#define MTOT  (BATCH*SEQ)

// ---- scratch ----
__device__ float g_q[MTOT * DIM];
__device__ float g_k[MTOT * DIM];
__device__ float g_v[MTOT * DIM];
__device__ float g_ctx[MTOT * DIM];
__device__ float g_r[(size_t)BATCH * SEQ * SEQ];  // 1/Z
__device__ float g_x[MTOT * DIM];                 // tf32-rounded x
__device__ float g_w[4 * DIM * DIM];              // tf32-rounded weights

// ---- helpers ----
__device__ __forceinline__ uint32_t f2tf(float x) {
    uint32_t u;
    asm("cvt.rna.tf32.f32 %0, %1;" : "=r"(u) : "f"(x));
    return u;
}
__device__ __forceinline__ uint32_t ldbits(const float* p) { return __float_as_uint(*p); }

__device__ __forceinline__ void mma8(float c[4], const uint32_t a[4], const uint32_t b[2]) {
    asm volatile(
        "mma.sync.aligned.m16n8k8.row.col.f32.tf32.tf32.f32 "
        "{%0,%1,%2,%3}, {%4,%5,%6,%7}, {%8,%9}, {%0,%1,%2,%3};\n"
        : "+f"(c[0]), "+f"(c[1]), "+f"(c[2]), "+f"(c[3])
        : "r"(a[0]), "r"(a[1]), "r"(a[2]), "r"(a[3]), "r"(b[0]), "r"(b[1]));
}
__device__ __forceinline__ void cpa16(float* s, const float* g) {
    uint32_t sa = (uint32_t)__cvta_generic_to_shared(s);
    asm volatile("cp.async.ca.shared.global [%0], [%1], 16;\n" ::"r"(sa), "l"(g));
}
__device__ __forceinline__ void cp_commit() { asm volatile("cp.async.commit_group;\n"); }
template <int N>
__device__ __forceinline__ void cp_wait() { asm volatile("cp.async.wait_group %0;\n" ::"n"(N)); }

// =====================================================================
// Elementwise tf32 rounding
// =====================================================================
__global__ void round_tf32(const float* __restrict__ in, float* __restrict__ out, int n4) {
    int i = blockIdx.x * blockDim.x + threadIdx.x;
    int stride = gridDim.x * blockDim.x;
    for (; i < n4; i += stride) {
        float4 v = ((const float4*)in)[i];
        v.x = __uint_as_float(f2tf(v.x));
        v.y = __uint_as_float(f2tf(v.y));
        v.z = __uint_as_float(f2tf(v.z));
        v.w = __uint_as_float(f2tf(v.w));
        ((float4*)out)[i] = v;
    }
}

__global__ void round_tf32_w4(const float* __restrict__ w0, const float* __restrict__ w1,
                              const float* __restrict__ w2, const float* __restrict__ w3,
                              float* __restrict__ out) {
    const float* src = (blockIdx.y == 0) ? w0 : (blockIdx.y == 1) ? w1 : (blockIdx.y == 2) ? w2 : w3;
    float* dst = out + (size_t)blockIdx.y * DIM * DIM;
    const int n4 = DIM * DIM / 4;
    int i = blockIdx.x * blockDim.x + threadIdx.x;
    int stride = gridDim.x * blockDim.x;
    for (; i < n4; i += stride) {
        float4 v = ((const float4*)src)[i];
        v.x = __uint_as_float(f2tf(v.x));
        v.y = __uint_as_float(f2tf(v.y));
        v.z = __uint_as_float(f2tf(v.z));
        v.w = __uint_as_float(f2tf(v.w));
        ((float4*)dst)[i] = v;
    }
}

// =====================================================================
// GEMM: C[M,1024] = A @ W.  Block 128x128x32, 8 warps (2m x 4n), warp 64x32.
// GS=3 -> 107 KB smem, <=128 regs -> 2 CTAs/SM (16 warps/SM).
// Inputs pre-rounded tf32.
// =====================================================================
#define GS 3
#define SA_ST (128 * 36)
#define SB_ST (32 * 136)
#define G_SMEM (GS * (SA_ST + SB_ST) * 4)

__global__ __launch_bounds__(256, 2) void gemm_tf32(const float* __restrict__ A,
                                                    const float* __restrict__ W,
                                                    float* __restrict__ C, int cvt_store) {
    extern __shared__ float sm[];
    float* sA = sm;
    float* sB = sm + GS * SA_ST;
    const int tid = threadIdx.x;
    const int m0 = blockIdx.y * 128, n0 = blockIdx.x * 128;
    const int w = tid >> 5, lane = tid & 31, g = lane >> 2, tg = lane & 3;
    const int wm = (w >> 2) * 64, wn = (w & 3) * 32;

    float acc[4][4][4]{};

    auto load_tile = [&](int st, int kt) {
        float* a = sA + st * SA_ST;
        float* b = sB + st * SB_ST;
#pragma unroll
        for (int i = 0; i < 4; i++) {
            int c = tid + 256 * i;
            int r = c >> 3, cc = (c & 7) * 4;
            cpa16(a + r * 36 + cc, A + (size_t)(m0 + r) * DIM + kt + cc);
        }
#pragma unroll
        for (int i = 0; i < 4; i++) {
            int c = tid + 256 * i;
            int r = c >> 5, cc = (c & 31) * 4;
            cpa16(b + r * 136 + cc, W + (size_t)(kt + r) * DIM + n0 + cc);
        }
    };

    const int NK = DIM / 32;
#pragma unroll
    for (int s = 0; s < GS - 1; s++) {
        load_tile(s, s * 32);
        cp_commit();
    }
    for (int t = 0; t < NK; t++) {
        cp_wait<GS - 2>();
        __syncthreads();
        int ld = t + GS - 1;
        if (ld < NK) load_tile(ld % GS, ld * 32);
        cp_commit();
        const float* a = sA + (t % GS) * SA_ST;
        const float* b = sB + (t % GS) * SB_ST;
#pragma unroll
        for (int kk = 0; kk < 32; kk += 8) {
            uint32_t af[4][4], bf[4][2];
#pragma unroll
            for (int mt = 0; mt < 4; mt++) {
                int r = wm + mt * 16;
                af[mt][0] = ldbits(a + (r + g) * 36 + kk + tg);
                af[mt][1] = ldbits(a + (r + g + 8) * 36 + kk + tg);
                af[mt][2] = ldbits(a + (r + g) * 36 + kk + tg + 4);
                af[mt][3] = ldbits(a + (r + g + 8) * 36 + kk + tg + 4);
            }
#pragma unroll
            for (int nt = 0; nt < 4; nt++) {
                int nb = wn + nt * 8;
                bf[nt][0] = ldbits(b + (kk + tg) * 136 + nb + g);
                bf[nt][1] = ldbits(b + (kk + tg + 4) * 136 + nb + g);
            }
#pragma unroll
            for (int mt = 0; mt < 4; mt++)
#pragma unroll
                for (int nt = 0; nt < 4; nt++) mma8(acc[mt][nt], af[mt], bf[nt]);
        }
    }
#pragma unroll
    for (int mt = 0; mt < 4; mt++)
#pragma unroll
        for (int nt = 0; nt < 4; nt++) {
            int row = m0 + wm + mt * 16 + g;
            int col = n0 + wn + nt * 8 + 2 * tg;
            float e[4];
#pragma unroll
            for (int i = 0; i < 4; i++)
                e[i] = cvt_store ? __uint_as_float(f2tf(acc[mt][nt][i])) : acc[mt][nt][i];
            *(float2*)(C + (size_t)row * DIM + col) = make_float2(e[0], e[1]);
            *(float2*)(C + (size_t)(row + 8) * DIM + col) = make_float2(e[2], e[3]);
        }
}

// =====================================================================
// Pass A: R[b,q,k] = 1 / sum_h exp(scale * q_h . k_h)
// 128x128 tile, 8 warps (2m x 4n, 64x32), per-head double buffer. (= R3)
// =====================================================================
#define ZT_ST (128 * 68)
#define Z_SMEM (4 * ZT_ST * 4)

__global__ __launch_bounds__(256) void attn_z() {
    extern __shared__ float sm[];
    float* sQ = sm;
    float* sK = sm + 2 * ZT_ST;
    const int tid = threadIdx.x;
    const int b = blockIdx.z, qt = blockIdx.y * 128, kt = blockIdx.x * 128;
    const int w = tid >> 5, lane = tid & 31, g = lane >> 2, tg = lane & 3;
    const int wm = (w >> 2) * 64, wn = (w & 3) * 32;

    const float* qb = g_q + (size_t)(b * SEQ + qt) * DIM;
    const float* kb = g_k + (size_t)(b * SEQ + kt) * DIM;

    auto load_head = [&](int st, int h) {
        float* q = sQ + st * ZT_ST;
        float* k = sK + st * ZT_ST;
#pragma unroll
        for (int i = 0; i < 8; i++) {
            int c = tid + 256 * i;
            int r = c >> 4, cc = (c & 15) * 4;
            cpa16(q + r * 68 + cc, qb + (size_t)r * DIM + h * HD + cc);
            cpa16(k + r * 68 + cc, kb + (size_t)r * DIM + h * HD + cc);
        }
    };

    float zacc[4][4][4]{};
    load_head(0, 0);
    cp_commit();

    for (int h = 0; h < NH; h++) {
        cp_wait<0>();
        __syncthreads();
        if (h + 1 < NH) load_head((h + 1) & 1, h + 1);
        cp_commit();
        const float* q = sQ + (h & 1) * ZT_ST;
        const float* k = sK + (h & 1) * ZT_ST;

        float sacc[4][4][4]{};
#pragma unroll
        for (int kk = 0; kk < 64; kk += 8) {
            uint32_t af[4][4], bf[4][2];
#pragma unroll
            for (int mt = 0; mt < 4; mt++) {
                int r = wm + mt * 16;
                af[mt][0] = ldbits(q + (r + g) * 68 + kk + tg);
                af[mt][1] = ldbits(q + (r + g + 8) * 68 + kk + tg);
                af[mt][2] = ldbits(q + (r + g) * 68 + kk + tg + 4);
                af[mt][3] = ldbits(q + (r + g + 8) * 68 + kk + tg + 4);
            }
#pragma unroll
            for (int nt = 0; nt < 4; nt++) {
                int nb = wn + nt * 8;
                bf[nt][0] = ldbits(k + (nb + g) * 68 + kk + tg);
                bf[nt][1] = ldbits(k + (nb + g) * 68 + kk + tg + 4);
            }
#pragma unroll
            for (int mt = 0; mt < 4; mt++)
#pragma unroll
                for (int nt = 0; nt < 4; nt++) mma8(sacc[mt][nt], af[mt], bf[nt]);
        }
#pragma unroll
        for (int i = 0; i < 4; i++)
#pragma unroll
            for (int j = 0; j < 4; j++)
#pragma unroll
                for (int e = 0; e < 4; e++) zacc[i][j][e] += __expf(sacc[i][j][e] * SCALE);
    }
#pragma unroll
    for (int mt = 0; mt < 4; mt++)
#pragma unroll
        for (int nt = 0; nt < 4; nt++) {
            int row = qt + wm + mt * 16 + g;
            int col = kt + wn + nt * 8 + 2 * tg;
            float* rp = g_r + ((size_t)b * SEQ + row) * SEQ + col;
            *(float2*)rp = make_float2(1.f / zacc[mt][nt][0], 1.f / zacc[mt][nt][1]);
            *(float2*)(rp + (size_t)8 * SEQ) = make_float2(1.f / zacc[mt][nt][2], 1.f / zacc[mt][nt][3]);
        }
}

// =====================================================================
// Pass B: ctx = sum_k exp(scale*S)*R * V  per (b,h,qtile). (= R3)
// GEMM1: 8 warps 2m x 4n (64x32). GEMM2: 2m x 2n x 2ksplit (64x32).
// =====================================================================
#define CQ_ST (128 * 68)
#define CV_ST (128 * 72)
#define CP_ST (128 * 132)
#define C_SMEM ((3 * CQ_ST + CV_ST + CP_ST) * 4)

__global__ __launch_bounds__(256) void attn_ctx() {
    extern __shared__ float sm[];
    float* sQ = sm;
    float* sK = sm + CQ_ST;  // [2]
    float* sV = sm + 3 * CQ_ST;
    float* sP = sV + CV_ST;

    const int tid = threadIdx.x;
    const int b = blockIdx.z, h = blockIdx.y, qt = blockIdx.x * 128;
    const int w = tid >> 5, lane = tid & 31, g = lane >> 2, tg = lane & 3;
    const int wm = (w >> 2) * 64, wn = (w & 3) * 32;
    const int wk2 = (w >> 1) & 1, wn2 = (w & 1) * 32;  // GEMM2 k-split / n

    const float* qb = g_q + (size_t)(b * SEQ + qt) * DIM + h * HD;
#pragma unroll
    for (int i = 0; i < 8; i++) {
        int c = tid + 256 * i;
        int r = c >> 4, cc = (c & 15) * 4;
        cpa16(sQ + r * 68 + cc, qb + (size_t)r * DIM + cc);
    }
    {
        const float* kb = g_k + (size_t)(b * SEQ) * DIM + h * HD;
#pragma unroll
        for (int i = 0; i < 8; i++) {
            int c = tid + 256 * i;
            int r = c >> 4, cc = (c & 15) * 4;
            cpa16(sK + r * 68 + cc, kb + (size_t)r * DIM + cc);
        }
    }
    cp_commit();

    float cacc[4][4][4]{};

    for (int t = 0; t < SEQ / 128; t++) {
        const int kt = t * 128;
        {
            const float* vb = g_v + (size_t)(b * SEQ + kt) * DIM + h * HD;
#pragma unroll
            for (int i = 0; i < 8; i++) {
                int c = tid + 256 * i;
                int r = c >> 4, cc = (c & 15) * 4;
                cpa16(sV + r * 72 + cc, vb + (size_t)r * DIM + cc);
            }
            const float* rb = g_r + ((size_t)b * SEQ + qt) * SEQ + kt;
#pragma unroll
            for (int i = 0; i < 16; i++) {
                int c = tid + 256 * i;
                int r = c >> 5, cc = (c & 31) * 4;
                cpa16(sP + r * 132 + cc, rb + (size_t)r * SEQ + cc);
            }
        }
        cp_commit();
        cp_wait<1>();  // K(t) (and Q) ready
        __syncthreads();

        {
            int ktn = (t + 1 < SEQ / 128) ? kt + 128 : 0;
            const float* kb = g_k + (size_t)(b * SEQ + ktn) * DIM + h * HD;
            float* kd = sK + ((t + 1) & 1) * CQ_ST;
#pragma unroll
            for (int i = 0; i < 8; i++) {
                int c = tid + 256 * i;
                int r = c >> 4, cc = (c & 15) * 4;
                cpa16(kd + r * 68 + cc, kb + (size_t)r * DIM + cc);
            }
        }
        cp_commit();

        // GEMM1: S = Q @ K^T (128x128x64)
        const float* kc = sK + (t & 1) * CQ_ST;
        float sacc[4][4][4]{};
#pragma unroll
        for (int kk = 0; kk < 64; kk += 8) {
            uint32_t af[4][4], bf[4][2];
#pragma unroll
            for (int mt = 0; mt < 4; mt++) {
                int r = wm + mt * 16;
                af[mt][0] = ldbits(sQ + (r + g) * 68 + kk + tg);
                af[mt][1] = ldbits(sQ + (r + g + 8) * 68 + kk + tg);
                af[mt][2] = ldbits(sQ + (r + g) * 68 + kk + tg + 4);
                af[mt][3] = ldbits(sQ + (r + g + 8) * 68 + kk + tg + 4);
            }
#pragma unroll
            for (int nt = 0; nt < 4; nt++) {
                int nb = wn + nt * 8;
                bf[nt][0] = ldbits(kc + (nb + g) * 68 + kk + tg);
                bf[nt][1] = ldbits(kc + (nb + g) * 68 + kk + tg + 4);
            }
#pragma unroll
            for (int mt = 0; mt < 4; mt++)
#pragma unroll
                for (int nt = 0; nt < 4; nt++) mma8(sacc[mt][nt], af[mt], bf[nt]);
        }

        cp_wait<1>();  // V(t), R(t) ready
        __syncthreads();

        // P = tf32(exp(scale*S) * R), in-place in sP
#pragma unroll
        for (int mt = 0; mt < 4; mt++)
#pragma unroll
            for (int nt = 0; nt < 4; nt++) {
                int row = wm + mt * 16 + g;
                int col = wn + nt * 8 + 2 * tg;
                float2* p0 = (float2*)(sP + row * 132 + col);
                float2* p1 = (float2*)(sP + (row + 8) * 132 + col);
                float2 r0 = *p0, r1 = *p1;
                *p0 = make_float2(__uint_as_float(f2tf(__expf(sacc[mt][nt][0] * SCALE) * r0.x)),
                                  __uint_as_float(f2tf(__expf(sacc[mt][nt][1] * SCALE) * r0.y)));
                *p1 = make_float2(__uint_as_float(f2tf(__expf(sacc[mt][nt][2] * SCALE) * r1.x)),
                                  __uint_as_float(f2tf(__expf(sacc[mt][nt][3] * SCALE) * r1.y)));
            }
        __syncthreads();

        // GEMM2: ctx += P @ V  (128x64x128, k-split over warps)
#pragma unroll
        for (int kk = 0; kk < 64; kk += 8) {
            const int kx = wk2 * 64 + kk;
            uint32_t af[4][4], bf[4][2];
#pragma unroll
            for (int mt = 0; mt < 4; mt++) {
                int r = wm + mt * 16;
                af[mt][0] = ldbits(sP + (r + g) * 132 + kx + tg);
                af[mt][1] = ldbits(sP + (r + g + 8) * 132 + kx + tg);
                af[mt][2] = ldbits(sP + (r + g) * 132 + kx + tg + 4);
                af[mt][3] = ldbits(sP + (r + g + 8) * 132 + kx + tg + 4);
            }
#pragma unroll
            for (int nt = 0; nt < 4; nt++) {
                int nb = wn2 + nt * 8;
                bf[nt][0] = ldbits(sV + (kx + tg) * 72 + nb + g);
                bf[nt][1] = ldbits(sV + (kx + tg + 4) * 72 + nb + g);
            }
#pragma unroll
            for (int mt = 0; mt < 4; mt++)
#pragma unroll
                for (int nt = 0; nt < 4; nt++) mma8(cacc[mt][nt], af[mt], bf[nt]);
        }
        __syncthreads();
    }

    // reduce k-split partials via sP
    if (wk2 == 1) {
#pragma unroll
        for (int mt = 0; mt < 4; mt++)
#pragma unroll
            for (int nt = 0; nt < 4; nt++) {
                int row = wm + mt * 16 + g;
                int col = wn2 + nt * 8 + 2 * tg;
                *(float2*)(sP + row * 132 + col) = make_float2(cacc[mt][nt][0], cacc[mt][nt][1]);
                *(float2*)(sP + (row + 8) * 132 + col) = make_float2(cacc[mt][nt][2], cacc[mt][nt][3]);
            }
    }
    __syncthreads();
    if (wk2 == 0) {
        float* cb = g_ctx + (size_t)(b * SEQ + qt) * DIM + h * HD;
#pragma unroll
        for (int mt = 0; mt < 4; mt++)
#pragma unroll
            for (int nt = 0; nt < 4; nt++) {
                int row = wm + mt * 16 + g;
                int col = wn2 + nt * 8 + 2 * tg;
                float2 o0 = *(float2*)(sP + row * 132 + col);
                float2 o1 = *(float2*)(sP + (row + 8) * 132 + col);
                o0.x += cacc[mt][nt][0];
                o0.y += cacc[mt][nt][1];
                o1.x += cacc[mt][nt][2];
                o1.y += cacc[mt][nt][3];
                *(float2*)(cb + (size_t)row * DIM + col) =
                    make_float2(__uint_as_float(f2tf(o0.x)), __uint_as_float(f2tf(o0.y)));
                *(float2*)(cb + (size_t)(row + 8) * DIM + col) =
                    make_float2(__uint_as_float(f2tf(o1.x)), __uint_as_float(f2tf(o1.y)));
            }
    }
}

// =====================================================================
extern "C" void kernel_launch(void* const* d_in, const int* in_sizes, int n_in,
                              void* d_out, int out_size) {
    const float* x = (const float*)d_in[0];
    const float* wq = (const float*)d_in[1];
    const float* wk = (const float*)d_in[2];
    const float* wv = (const float*)d_in[3];
    const float* wo = (const float*)d_in[4];
    float* out = (float*)d_out;

    float *q, *k, *v, *ctx, *xr, *wr;
    cudaGetSymbolAddress((void**)&q, g_q);
    cudaGetSymbolAddress((void**)&k, g_k);
    cudaGetSymbolAddress((void**)&v, g_v);
    cudaGetSymbolAddress((void**)&ctx, g_ctx);
    cudaGetSymbolAddress((void**)&xr, g_x);
    cudaGetSymbolAddress((void**)&wr, g_w);

    static int attr_done = 0;
    if (!attr_done) {
        cudaFuncSetAttribute(gemm_tf32, cudaFuncAttributeMaxDynamicSharedMemorySize, G_SMEM);
        cudaFuncSetAttribute(attn_z, cudaFuncAttributeMaxDynamicSharedMemorySize, Z_SMEM);
        cudaFuncSetAttribute(attn_ctx, cudaFuncAttributeMaxDynamicSharedMemorySize, C_SMEM);
        attr_done = 1;
    }

    round_tf32<<<2048, 256>>>(x, xr, MTOT * DIM / 4);
    round_tf32_w4<<<dim3(256, 4), 256>>>(wq, wk, wv, wo, wr);

    dim3 gg(DIM / 128, MTOT / 128);  // (8, 64)
    gemm_tf32<<<gg, 256, G_SMEM>>>(xr, wr + 0 * DIM * DIM, q, 1);
    gemm_tf32<<<gg, 256, G_SMEM>>>(xr, wr + 1 * DIM * DIM, k, 1);
    gemm_tf32<<<gg, 256, G_SMEM>>>(xr, wr + 2 * DIM * DIM, v, 1);

    attn_z<<<dim3(SEQ / 128, SEQ / 128, BATCH), 256, Z_SMEM>>>();

    attn_ctx<<<dim3(SEQ / 128, NH, BATCH), 256, C_SMEM>>>();

    gemm_tf32<<<gg, 256, G_SMEM>>>(ctx, wr + 3 * DIM * DIM, out, 0);
}

// round 7
// speedup vs baseline: 1.8317x; 1.7868x over previous
#include <cuda_runtime.h>
#include <cuda_fp16.h>
#include <stdint.h>

#define BATCH 4
#define SEQ   2048
#define DIM   1024
#define NH    16
#define HD    64
#define SCALE 0.125f
#define MTOT  (BATCH*SEQ)

// ---- scratch ----
__device__ __half g_q[MTOT * DIM];
__device__ __half g_k[MTOT * DIM];
__device__ __half g_v[MTOT * DIM];    // [b*S+s][n]  (temp)
__device__ __half g_vT[MTOT * DIM];   // [(b*NH+h)*HD+d][s]
__device__ __half g_ctx[MTOT * DIM];
__device__ __half g_x[MTOT * DIM];
__device__ __half g_w[4 * DIM * DIM]; // W^T, [n][k]
__device__ float g_r[(size_t)BATCH * SEQ * SEQ];  // 1/Z

// ---- helpers ----
__device__ __forceinline__ uint32_t h2u(float a, float b) {
    __half2 h = __floats2half2_rn(a, b);
    return *(uint32_t*)&h;
}
__device__ __forceinline__ void mma16(float c[4], const uint32_t a[4], const uint32_t b[2]) {
    asm volatile(
        "mma.sync.aligned.m16n8k16.row.col.f32.f16.f16.f32 "
        "{%0,%1,%2,%3}, {%4,%5,%6,%7}, {%8,%9}, {%0,%1,%2,%3};\n"
        : "+f"(c[0]), "+f"(c[1]), "+f"(c[2]), "+f"(c[3])
        : "r"(a[0]), "r"(a[1]), "r"(a[2]), "r"(a[3]), "r"(b[0]), "r"(b[1]));
}
__device__ __forceinline__ void cpa16(void* s, const void* g) {
    uint32_t sa = (uint32_t)__cvta_generic_to_shared(s);
    asm volatile("cp.async.ca.shared.global [%0], [%1], 16;\n" ::"r"(sa), "l"(g));
}
__device__ __forceinline__ void cp_commit() { asm volatile("cp.async.commit_group;\n"); }
template <int N>
__device__ __forceinline__ void cp_wait() { asm volatile("cp.async.wait_group %0;\n" ::"n"(N)); }

// =====================================================================
// x -> fp16
// =====================================================================
__global__ void round_x_h(const float* __restrict__ x) {
    const int n4 = MTOT * DIM / 4;
    uint2* out = (uint2*)g_x;
    int i = blockIdx.x * blockDim.x + threadIdx.x;
    int stride = gridDim.x * blockDim.x;
    for (; i < n4; i += stride) {
        float4 v = ((const float4*)x)[i];
        uint2 o;
        o.x = h2u(v.x, v.y);
        o.y = h2u(v.z, v.w);
        out[i] = o;
    }
}

// =====================================================================
// weights -> fp16, transposed to [n][k]
// =====================================================================
__global__ void round_w_t(const float* __restrict__ w0, const float* __restrict__ w1,
                          const float* __restrict__ w2, const float* __restrict__ w3) {
    __shared__ float t[32][33];
    const float* src = (blockIdx.z == 0) ? w0 : (blockIdx.z == 1) ? w1 : (blockIdx.z == 2) ? w2 : w3;
    __half* dst = g_w + (size_t)blockIdx.z * DIM * DIM;
    const int k0 = blockIdx.y * 32, n0 = blockIdx.x * 32;
    const int r = threadIdx.x >> 5, cc = threadIdx.x & 31;
#pragma unroll
    for (int i = 0; i < 4; i++) t[r + i * 8][cc] = src[(size_t)(k0 + r + i * 8) * DIM + n0 + cc];
    __syncthreads();
#pragma unroll
    for (int i = 0; i < 4; i++)
        dst[(size_t)(n0 + r + i * 8) * DIM + k0 + cc] = __float2half_rn(t[cc][r + i * 8]);
}

// =====================================================================
// v [s][n] -> vT [n][s], per batch
// =====================================================================
__global__ void transpose_v() {
    __shared__ __half t[32][33];
    const int b = blockIdx.z, s0 = blockIdx.x * 32, n0 = blockIdx.y * 32;
    const int r = threadIdx.x >> 5, cc = threadIdx.x & 31;
#pragma unroll
    for (int i = 0; i < 4; i++)
        t[r + i * 8][cc] = g_v[(size_t)(b * SEQ + s0 + r + i * 8) * DIM + n0 + cc];
    __syncthreads();
#pragma unroll
    for (int i = 0; i < 4; i++)
        g_vT[((size_t)b * DIM + n0 + r + i * 8) * SEQ + s0 + cc] = t[cc][r + i * 8];
}

// =====================================================================
// GEMM: C[M,1024] = A @ W  (A fp16 [m][k], W given as W^T fp16 [n][k]).
// Block 128x256, k-stage 64, 8 warps (2m x 4n), warp 64x64, GS=3.
// =====================================================================
#define GS 3
#define GA_W (128 * 36)
#define GB_W (256 * 36)
#define G_SMEM (GS * (GA_W + GB_W) * 4)

__global__ __launch_bounds__(256) void gemm_fp16(const __half* __restrict__ A,
                                                 const __half* __restrict__ WT,
                                                 void* __restrict__ Cout, int half_out) {
    extern __shared__ uint32_t smu[];
    uint32_t* sA = smu;
    uint32_t* sB = smu + GS * GA_W;
    const int tid = threadIdx.x;
    const int m0 = blockIdx.y * 128, n0 = blockIdx.x * 256;
    const int w = tid >> 5, lane = tid & 31, g = lane >> 2, tg = lane & 3;
    const int wm = (w >> 2) * 64, wn = (w & 3) * 64;

    float acc[4][8][4]{};

    auto load_tile = [&](int st, int kt) {
        uint32_t* a = sA + st * GA_W;
        uint32_t* bb = sB + st * GB_W;
#pragma unroll
        for (int i = 0; i < 4; i++) {
            int c = tid + 256 * i;
            int r = c >> 3, cw = (c & 7) * 4;
            cpa16(a + r * 36 + cw, A + (size_t)(m0 + r) * DIM + kt + cw * 2);
        }
#pragma unroll
        for (int i = 0; i < 8; i++) {
            int c = tid + 256 * i;
            int r = c >> 3, cw = (c & 7) * 4;
            cpa16(bb + r * 36 + cw, WT + (size_t)(n0 + r) * DIM + kt + cw * 2);
        }
    };

    const int NK = DIM / 64;  // 16
#pragma unroll
    for (int s = 0; s < GS - 1; s++) {
        load_tile(s, s * 64);
        cp_commit();
    }
    for (int t = 0; t < NK; t++) {
        cp_wait<GS - 2>();
        __syncthreads();
        int ld = t + GS - 1;
        if (ld < NK) load_tile(ld % GS, ld * 64);
        cp_commit();
        const uint32_t* a = sA + (t % GS) * GA_W;
        const uint32_t* b = sB + (t % GS) * GB_W;
#pragma unroll
        for (int kw = 0; kw < 32; kw += 8) {
            uint32_t af[4][4], bf[8][2];
#pragma unroll
            for (int mt = 0; mt < 4; mt++) {
                int r = wm + mt * 16;
                af[mt][0] = a[(r + g) * 36 + kw + tg];
                af[mt][1] = a[(r + g + 8) * 36 + kw + tg];
                af[mt][2] = a[(r + g) * 36 + kw + tg + 4];
                af[mt][3] = a[(r + g + 8) * 36 + kw + tg + 4];
            }
#pragma unroll
            for (int nt = 0; nt < 8; nt++) {
                int nb = wn + nt * 8;
                bf[nt][0] = b[(nb + g) * 36 + kw + tg];
                bf[nt][1] = b[(nb + g) * 36 + kw + tg + 4];
            }
#pragma unroll
            for (int mt = 0; mt < 4; mt++)
#pragma unroll
                for (int nt = 0; nt < 8; nt++) mma16(acc[mt][nt], af[mt], bf[nt]);
        }
    }
#pragma unroll
    for (int mt = 0; mt < 4; mt++)
#pragma unroll
        for (int nt = 0; nt < 8; nt++) {
            int row = m0 + wm + mt * 16 + g;
            int col = n0 + wn + nt * 8 + 2 * tg;
            if (half_out) {
                __half* C = (__half*)Cout;
                *(uint32_t*)(C + (size_t)row * DIM + col) = h2u(acc[mt][nt][0], acc[mt][nt][1]);
                *(uint32_t*)(C + (size_t)(row + 8) * DIM + col) = h2u(acc[mt][nt][2], acc[mt][nt][3]);
            } else {
                float* C = (float*)Cout;
                *(float2*)(C + (size_t)row * DIM + col) = make_float2(acc[mt][nt][0], acc[mt][nt][1]);
                *(float2*)(C + (size_t)(row + 8) * DIM + col) = make_float2(acc[mt][nt][2], acc[mt][nt][3]);
            }
        }
}

// =====================================================================
// Pass A: R[b,q,k] = 1 / sum_h exp(scale * q_h . k_h)   (fp16 MMA)
// =====================================================================
#define ZT_W (128 * 36)
#define Z_SMEM (4 * ZT_W * 4)

__global__ __launch_bounds__(256) void attn_z() {
    extern __shared__ uint32_t smu[];
    uint32_t* sQ = smu;
    uint32_t* sK = smu + 2 * ZT_W;
    const int tid = threadIdx.x;
    const int b = blockIdx.z, qt = blockIdx.y * 128, kt = blockIdx.x * 128;
    const int w = tid >> 5, lane = tid & 31, g = lane >> 2, tg = lane & 3;
    const int wm = (w >> 2) * 64, wn = (w & 3) * 32;

    const __half* qb = g_q + (size_t)(b * SEQ + qt) * DIM;
    const __half* kb = g_k + (size_t)(b * SEQ + kt) * DIM;

    auto load_head = [&](int st, int h) {
        uint32_t* q = sQ + st * ZT_W;
        uint32_t* k = sK + st * ZT_W;
#pragma unroll
        for (int i = 0; i < 4; i++) {
            int c = tid + 256 * i;
            int r = c >> 3, cw = (c & 7) * 4;
            cpa16(q + r * 36 + cw, qb + (size_t)r * DIM + h * HD + cw * 2);
            cpa16(k + r * 36 + cw, kb + (size_t)r * DIM + h * HD + cw * 2);
        }
    };

    float zacc[4][4][4]{};
    load_head(0, 0);
    cp_commit();

    for (int h = 0; h < NH; h++) {
        cp_wait<0>();
        __syncthreads();
        if (h + 1 < NH) load_head((h + 1) & 1, h + 1);
        cp_commit();
        const uint32_t* q = sQ + (h & 1) * ZT_W;
        const uint32_t* k = sK + (h & 1) * ZT_W;

        float sacc[4][4][4]{};
#pragma unroll
        for (int kw = 0; kw < 32; kw += 8) {
            uint32_t af[4][4], bf[4][2];
#pragma unroll
            for (int mt = 0; mt < 4; mt++) {
                int r = wm + mt * 16;
                af[mt][0] = q[(r + g) * 36 + kw + tg];
                af[mt][1] = q[(r + g + 8) * 36 + kw + tg];
                af[mt][2] = q[(r + g) * 36 + kw + tg + 4];
                af[mt][3] = q[(r + g + 8) * 36 + kw + tg + 4];
            }
#pragma unroll
            for (int nt = 0; nt < 4; nt++) {
                int nb = wn + nt * 8;
                bf[nt][0] = k[(nb + g) * 36 + kw + tg];
                bf[nt][1] = k[(nb + g) * 36 + kw + tg + 4];
            }
#pragma unroll
            for (int mt = 0; mt < 4; mt++)
#pragma unroll
                for (int nt = 0; nt < 4; nt++) mma16(sacc[mt][nt], af[mt], bf[nt]);
        }
#pragma unroll
        for (int i = 0; i < 4; i++)
#pragma unroll
            for (int j = 0; j < 4; j++)
#pragma unroll
                for (int e = 0; e < 4; e++) zacc[i][j][e] += __expf(sacc[i][j][e] * SCALE);
    }
#pragma unroll
    for (int mt = 0; mt < 4; mt++)
#pragma unroll
        for (int nt = 0; nt < 4; nt++) {
            int row = qt + wm + mt * 16 + g;
            int col = kt + wn + nt * 8 + 2 * tg;
            float* rp = g_r + ((size_t)b * SEQ + row) * SEQ + col;
            *(float2*)rp = make_float2(1.f / zacc[mt][nt][0], 1.f / zacc[mt][nt][1]);
            *(float2*)(rp + (size_t)8 * SEQ) = make_float2(1.f / zacc[mt][nt][2], 1.f / zacc[mt][nt][3]);
        }
}

// =====================================================================
// Pass B: ctx = sum_k exp(scale*S)*R * V  per (b,h,qtile)  (fp16 MMA)
// =====================================================================
#define CQ_W (128 * 36)
#define CVT_W (64 * 68)
#define CP_W (128 * 68)
#define CR_W (128 * 132)
#define C_SMEM ((3 * CQ_W + CVT_W + CP_W + CR_W) * 4)

__global__ __launch_bounds__(256) void attn_ctx() {
    extern __shared__ uint32_t smu[];
    uint32_t* sQ = smu;
    uint32_t* sK = smu + CQ_W;  // [2]
    uint32_t* sVT = smu + 3 * CQ_W;
    uint32_t* sP = sVT + CVT_W;
    float* sR = (float*)(sP + CP_W);

    const int tid = threadIdx.x;
    const int b = blockIdx.z, h = blockIdx.y, qt = blockIdx.x * 128;
    const int w = tid >> 5, lane = tid & 31, g = lane >> 2, tg = lane & 3;
    const int wm = (w >> 2) * 64, wn = (w & 3) * 32;
    const int wk2 = (w >> 1) & 1, wn2 = (w & 1) * 32;

    const __half* qb = g_q + (size_t)(b * SEQ + qt) * DIM + h * HD;
#pragma unroll
    for (int i = 0; i < 4; i++) {
        int c = tid + 256 * i;
        int r = c >> 3, cw = (c & 7) * 4;
        cpa16(sQ + r * 36 + cw, qb + (size_t)r * DIM + cw * 2);
    }
    {
        const __half* kb = g_k + (size_t)(b * SEQ) * DIM + h * HD;
#pragma unroll
        for (int i = 0; i < 4; i++) {
            int c = tid + 256 * i;
            int r = c >> 3, cw = (c & 7) * 4;
            cpa16(sK + r * 36 + cw, kb + (size_t)r * DIM + cw * 2);
        }
    }
    cp_commit();

    float cacc[4][4][4]{};

    for (int t = 0; t < SEQ / 128; t++) {
        const int kt = t * 128;
        {
            const __half* vtb = g_vT + ((size_t)(b * NH + h) * HD) * SEQ + kt;
#pragma unroll
            for (int i = 0; i < 4; i++) {
                int c = tid + 256 * i;
                int r = c >> 4, cw = (c & 15) * 4;
                cpa16(sVT + r * 68 + cw, vtb + (size_t)r * SEQ + cw * 2);
            }
            const float* rb = g_r + ((size_t)b * SEQ + qt) * SEQ + kt;
#pragma unroll
            for (int i = 0; i < 16; i++) {
                int c = tid + 256 * i;
                int r = c >> 5, cw = (c & 31) * 4;
                cpa16(sR + r * 132 + cw, rb + (size_t)r * SEQ + cw);
            }
        }
        cp_commit();
        cp_wait<1>();  // K(t) (and Q) ready
        __syncthreads();

        {
            int ktn = (t + 1 < SEQ / 128) ? kt + 128 : 0;
            const __half* kb = g_k + (size_t)(b * SEQ + ktn) * DIM + h * HD;
            uint32_t* kd = sK + ((t + 1) & 1) * CQ_W;
#pragma unroll
            for (int i = 0; i < 4; i++) {
                int c = tid + 256 * i;
                int r = c >> 3, cw = (c & 7) * 4;
                cpa16(kd + r * 36 + cw, kb + (size_t)r * DIM + cw * 2);
            }
        }
        cp_commit();

        // GEMM1: S = Q @ K^T (128x128x64)
        const uint32_t* kc = sK + (t & 1) * CQ_W;
        float sacc[4][4][4]{};
#pragma unroll
        for (int kw = 0; kw < 32; kw += 8) {
            uint32_t af[4][4], bf[4][2];
#pragma unroll
            for (int mt = 0; mt < 4; mt++) {
                int r = wm + mt * 16;
                af[mt][0] = sQ[(r + g) * 36 + kw + tg];
                af[mt][1] = sQ[(r + g + 8) * 36 + kw + tg];
                af[mt][2] = sQ[(r + g) * 36 + kw + tg + 4];
                af[mt][3] = sQ[(r + g + 8) * 36 + kw + tg + 4];
            }
#pragma unroll
            for (int nt = 0; nt < 4; nt++) {
                int nb = wn + nt * 8;
                bf[nt][0] = kc[(nb + g) * 36 + kw + tg];
                bf[nt][1] = kc[(nb + g) * 36 + kw + tg + 4];
            }
#pragma unroll
            for (int mt = 0; mt < 4; mt++)
#pragma unroll
                for (int nt = 0; nt < 4; nt++) mma16(sacc[mt][nt], af[mt], bf[nt]);
        }

        cp_wait<1>();  // V(t), R(t) ready
        __syncthreads();

        // P = fp16(exp(scale*S) * R) into sP
#pragma unroll
        for (int mt = 0; mt < 4; mt++)
#pragma unroll
            for (int nt = 0; nt < 4; nt++) {
                int row = wm + mt * 16 + g;
                int colh = wn + nt * 8 + 2 * tg;
                float r00 = sR[row * 132 + colh], r01 = sR[row * 132 + colh + 1];
                float r10 = sR[(row + 8) * 132 + colh], r11 = sR[(row + 8) * 132 + colh + 1];
                sP[row * 68 + (colh >> 1)] =
                    h2u(__expf(sacc[mt][nt][0] * SCALE) * r00, __expf(sacc[mt][nt][1] * SCALE) * r01);
                sP[(row + 8) * 68 + (colh >> 1)] =
                    h2u(__expf(sacc[mt][nt][2] * SCALE) * r10, __expf(sacc[mt][nt][3] * SCALE) * r11);
            }
        __syncthreads();

        // GEMM2: ctx += P @ V (128x64x128, k-split over warps)
#pragma unroll
        for (int kw = 0; kw < 32; kw += 8) {
            const int kx = wk2 * 32 + kw;
            uint32_t af[4][4], bf[4][2];
#pragma unroll
            for (int mt = 0; mt < 4; mt++) {
                int r = wm + mt * 16;
                af[mt][0] = sP[(r + g) * 68 + kx + tg];
                af[mt][1] = sP[(r + g + 8) * 68 + kx + tg];
                af[mt][2] = sP[(r + g) * 68 + kx + tg + 4];
                af[mt][3] = sP[(r + g + 8) * 68 + kx + tg + 4];
            }
#pragma unroll
            for (int nt = 0; nt < 4; nt++) {
                int nb = wn2 + nt * 8;
                bf[nt][0] = sVT[(nb + g) * 68 + kx + tg];
                bf[nt][1] = sVT[(nb + g) * 68 + kx + tg + 4];
            }
#pragma unroll
            for (int mt = 0; mt < 4; mt++)
#pragma unroll
                for (int nt = 0; nt < 4; nt++) mma16(cacc[mt][nt], af[mt], bf[nt]);
        }
        __syncthreads();
    }

    // reduce k-split partials via sR (free now)
    if (wk2 == 1) {
#pragma unroll
        for (int mt = 0; mt < 4; mt++)
#pragma unroll
            for (int nt = 0; nt < 4; nt++) {
                int row = wm + mt * 16 + g;
                int col = wn2 + nt * 8 + 2 * tg;
                *(float2*)&sR[row * 132 + col] = make_float2(cacc[mt][nt][0], cacc[mt][nt][1]);
                *(float2*)&sR[(row + 8) * 132 + col] = make_float2(cacc[mt][nt][2], cacc[mt][nt][3]);
            }
    }
    __syncthreads();
    if (wk2 == 0) {
        __half* cb = g_ctx + (size_t)(b * SEQ + qt) * DIM + h * HD;
#pragma unroll
        for (int mt = 0; mt < 4; mt++)
#pragma unroll
            for (int nt = 0; nt < 4; nt++) {
                int row = wm + mt * 16 + g;
                int col = wn2 + nt * 8 + 2 * tg;
                float2 o0 = *(float2*)&sR[row * 132 + col];
                float2 o1 = *(float2*)&sR[(row + 8) * 132 + col];
                *(uint32_t*)(cb + (size_t)row * DIM + col) =
                    h2u(o0.x + cacc[mt][nt][0], o0.y + cacc[mt][nt][1]);
                *(uint32_t*)(cb + (size_t)(row + 8) * DIM + col) =
                    h2u(o1.x + cacc[mt][nt][2], o1.y + cacc[mt][nt][3]);
            }
    }
}

// =====================================================================
extern "C" void kernel_launch(void* const* d_in, const int* in_sizes, int n_in,
                              void* d_out, int out_size) {
    const float* x = (const float*)d_in[0];
    const float* wq = (const float*)d_in[1];
    const float* wk = (const float*)d_in[2];
    const float* wv = (const float*)d_in[3];
    const float* wo = (const float*)d_in[4];
    float* out = (float*)d_out;

    __half *q, *k, *v, *ctx, *xr, *wr;
    cudaGetSymbolAddress((void**)&q, g_q);
    cudaGetSymbolAddress((void**)&k, g_k);
    cudaGetSymbolAddress((void**)&v, g_v);
    cudaGetSymbolAddress((void**)&ctx, g_ctx);
    cudaGetSymbolAddress((void**)&xr, g_x);
    cudaGetSymbolAddress((void**)&wr, g_w);

    static int attr_done = 0;
    if (!attr_done) {
        cudaFuncSetAttribute(gemm_fp16, cudaFuncAttributeMaxDynamicSharedMemorySize, G_SMEM);
        cudaFuncSetAttribute(attn_z, cudaFuncAttributeMaxDynamicSharedMemorySize, Z_SMEM);
        cudaFuncSetAttribute(attn_ctx, cudaFuncAttributeMaxDynamicSharedMemorySize, C_SMEM);
        attr_done = 1;
    }

    round_x_h<<<2048, 256>>>(x);
    round_w_t<<<dim3(32, 32, 4), 256>>>(wq, wk, wv, wo);

    dim3 gg(DIM / 256, MTOT / 128);  // (4, 64)
    gemm_fp16<<<gg, 256, G_SMEM>>>(xr, wr + 0 * DIM * DIM, q, 1);
    gemm_fp16<<<gg, 256, G_SMEM>>>(xr, wr + 1 * DIM * DIM, k, 1);
    gemm_fp16<<<gg, 256, G_SMEM>>>(xr, wr + 2 * DIM * DIM, v, 1);

    transpose_v<<<dim3(SEQ / 32, DIM / 32, BATCH), 256>>>();

    attn_z<<<dim3(SEQ / 128, SEQ / 128, BATCH), 256, Z_SMEM>>>();

    attn_ctx<<<dim3(SEQ / 128, NH, BATCH), 256, C_SMEM>>>();

    gemm_fp16<<<gg, 256, G_SMEM>>>(ctx, wr + 3 * DIM * DIM, out, 0);
}

// round 8
// speedup vs baseline: 2.0912x; 1.1417x over previous
#include <cuda_runtime.h>
#include <cuda_fp16.h>
#include <stdint.h>

#define BATCH 4
#define SEQ   2048
#define DIM   1024
#define NH    16
#define HD    64
#define SCALE 0.125f
#define MTOT  (BATCH*SEQ)

// ---- scratch ----
__device__ __half g_q[MTOT * DIM];
__device__ __half g_k[MTOT * DIM];
__device__ __half g_v[MTOT * DIM];    // [b*S+s][n]  (temp)
__device__ __half g_vT[MTOT * DIM];   // [(b*NH+h)*HD+d][s]
__device__ __half g_ctx[MTOT * DIM];
__device__ __half g_x[MTOT * DIM];
__device__ __half g_w[4 * DIM * DIM]; // W^T, [n][k]
__device__ __half g_r[(size_t)BATCH * SEQ * SEQ];  // 1/Z, fp16

// ---- helpers ----
__device__ __forceinline__ uint32_t h2u(float a, float b) {
    __half2 h = __floats2half2_rn(a, b);
    return *(uint32_t*)&h;
}
__device__ __forceinline__ void mma16(float c[4], const uint32_t a[4], const uint32_t b[2]) {
    asm volatile(
        "mma.sync.aligned.m16n8k16.row.col.f32.f16.f16.f32 "
        "{%0,%1,%2,%3}, {%4,%5,%6,%7}, {%8,%9}, {%0,%1,%2,%3};\n"
        : "+f"(c[0]), "+f"(c[1]), "+f"(c[2]), "+f"(c[3])
        : "r"(a[0]), "r"(a[1]), "r"(a[2]), "r"(a[3]), "r"(b[0]), "r"(b[1]));
}
__device__ __forceinline__ void ldsm4(uint32_t r[4], const uint32_t* p) {
    uint32_t a = (uint32_t)__cvta_generic_to_shared(p);
    asm volatile("ldmatrix.sync.aligned.m8n8.x4.shared.b16 {%0,%1,%2,%3}, [%4];\n"
                 : "=r"(r[0]), "=r"(r[1]), "=r"(r[2]), "=r"(r[3]) : "r"(a));
}
__device__ __forceinline__ void cpa16(void* s, const void* g) {
    uint32_t sa = (uint32_t)__cvta_generic_to_shared(s);
    asm volatile("cp.async.ca.shared.global [%0], [%1], 16;\n" ::"r"(sa), "l"(g));
}
__device__ __forceinline__ void cp_commit() { asm volatile("cp.async.commit_group;\n"); }
template <int N>
__device__ __forceinline__ void cp_wait() { asm volatile("cp.async.wait_group %0;\n" ::"n"(N)); }

// =====================================================================
// x -> fp16
// =====================================================================
__global__ void round_x_h(const float* __restrict__ x) {
    const int n4 = MTOT * DIM / 4;
    uint2* out = (uint2*)g_x;
    int i = blockIdx.x * blockDim.x + threadIdx.x;
    int stride = gridDim.x * blockDim.x;
    for (; i < n4; i += stride) {
        float4 v = ((const float4*)x)[i];
        uint2 o;
        o.x = h2u(v.x, v.y);
        o.y = h2u(v.z, v.w);
        out[i] = o;
    }
}

// =====================================================================
// weights -> fp16, transposed to [n][k]
// =====================================================================
__global__ void round_w_t(const float* __restrict__ w0, const float* __restrict__ w1,
                          const float* __restrict__ w2, const float* __restrict__ w3) {
    __shared__ float t[32][33];
    const float* src = (blockIdx.z == 0) ? w0 : (blockIdx.z == 1) ? w1 : (blockIdx.z == 2) ? w2 : w3;
    __half* dst = g_w + (size_t)blockIdx.z * DIM * DIM;
    const int k0 = blockIdx.y * 32, n0 = blockIdx.x * 32;
    const int r = threadIdx.x >> 5, cc = threadIdx.x & 31;
#pragma unroll
    for (int i = 0; i < 4; i++) t[r + i * 8][cc] = src[(size_t)(k0 + r + i * 8) * DIM + n0 + cc];
    __syncthreads();
#pragma unroll
    for (int i = 0; i < 4; i++)
        dst[(size_t)(n0 + r + i * 8) * DIM + k0 + cc] = __float2half_rn(t[cc][r + i * 8]);
}

// =====================================================================
// v [s][n] -> vT [n][s], per batch
// =====================================================================
__global__ void transpose_v() {
    __shared__ __half t[32][33];
    const int b = blockIdx.z, s0 = blockIdx.x * 32, n0 = blockIdx.y * 32;
    const int r = threadIdx.x >> 5, cc = threadIdx.x & 31;
#pragma unroll
    for (int i = 0; i < 4; i++)
        t[r + i * 8][cc] = g_v[(size_t)(b * SEQ + s0 + r + i * 8) * DIM + n0 + cc];
    __syncthreads();
#pragma unroll
    for (int i = 0; i < 4; i++)
        g_vT[((size_t)b * DIM + n0 + r + i * 8) * SEQ + s0 + cc] = t[cc][r + i * 8];
}

// =====================================================================
// GEMM: C[M,1024] = A @ W  (A fp16 [m][k], W given as W^T fp16 [n][k]).
// Block 128x256, k-stage 64, 8 warps (2m x 4n), warp 64x64, GS=3, LDSM.
// =====================================================================
#define GS 3
#define GA_W (128 * 36)
#define GB_W (256 * 36)
#define G_SMEM (GS * (GA_W + GB_W) * 4)

__global__ __launch_bounds__(256) void gemm_fp16(const __half* __restrict__ A,
                                                 const __half* __restrict__ WT,
                                                 void* __restrict__ Cout, int half_out) {
    extern __shared__ uint32_t smu[];
    uint32_t* sA = smu;
    uint32_t* sB = smu + GS * GA_W;
    const int tid = threadIdx.x;
    const int m0 = blockIdx.y * 128, n0 = blockIdx.x * 256;
    const int w = tid >> 5, lane = tid & 31, g = lane >> 2, tg = lane & 3;
    const int wm = (w >> 2) * 64, wn = (w & 3) * 64;
    const int lrA = (lane & 7) + ((lane >> 3) & 1) * 8, lcA = (lane >> 4) * 4;
    const int lrB = (lane & 7) + (lane >> 4) * 8, lcB = ((lane >> 3) & 1) * 4;

    float acc[4][8][4]{};

    auto load_tile = [&](int st, int kt) {
        uint32_t* a = sA + st * GA_W;
        uint32_t* bb = sB + st * GB_W;
#pragma unroll
        for (int i = 0; i < 4; i++) {
            int c = tid + 256 * i;
            int r = c >> 3, cw = (c & 7) * 4;
            cpa16(a + r * 36 + cw, A + (size_t)(m0 + r) * DIM + kt + cw * 2);
        }
#pragma unroll
        for (int i = 0; i < 8; i++) {
            int c = tid + 256 * i;
            int r = c >> 3, cw = (c & 7) * 4;
            cpa16(bb + r * 36 + cw, WT + (size_t)(n0 + r) * DIM + kt + cw * 2);
        }
    };

    const int NK = DIM / 64;  // 16
#pragma unroll
    for (int s = 0; s < GS - 1; s++) {
        load_tile(s, s * 64);
        cp_commit();
    }
    for (int t = 0; t < NK; t++) {
        cp_wait<GS - 2>();
        __syncthreads();
        int ld = t + GS - 1;
        if (ld < NK) load_tile(ld % GS, ld * 64);
        cp_commit();
        const uint32_t* a = sA + (t % GS) * GA_W;
        const uint32_t* b = sB + (t % GS) * GB_W;
#pragma unroll
        for (int kw = 0; kw < 32; kw += 8) {
            uint32_t af[4][4], bf[8][2];
#pragma unroll
            for (int mt = 0; mt < 4; mt++)
                ldsm4(af[mt], a + (wm + mt * 16 + lrA) * 36 + kw + lcA);
#pragma unroll
            for (int np = 0; np < 4; np++) {
                uint32_t tmp[4];
                ldsm4(tmp, b + (wn + np * 16 + lrB) * 36 + kw + lcB);
                bf[2 * np][0] = tmp[0];
                bf[2 * np][1] = tmp[1];
                bf[2 * np + 1][0] = tmp[2];
                bf[2 * np + 1][1] = tmp[3];
            }
#pragma unroll
            for (int mt = 0; mt < 4; mt++)
#pragma unroll
                for (int nt = 0; nt < 8; nt++) mma16(acc[mt][nt], af[mt], bf[nt]);
        }
    }
#pragma unroll
    for (int mt = 0; mt < 4; mt++)
#pragma unroll
        for (int nt = 0; nt < 8; nt++) {
            int row = m0 + wm + mt * 16 + g;
            int col = n0 + wn + nt * 8 + 2 * tg;
            if (half_out) {
                __half* C = (__half*)Cout;
                *(uint32_t*)(C + (size_t)row * DIM + col) = h2u(acc[mt][nt][0], acc[mt][nt][1]);
                *(uint32_t*)(C + (size_t)(row + 8) * DIM + col) = h2u(acc[mt][nt][2], acc[mt][nt][3]);
            } else {
                float* C = (float*)Cout;
                *(float2*)(C + (size_t)row * DIM + col) = make_float2(acc[mt][nt][0], acc[mt][nt][1]);
                *(float2*)(C + (size_t)(row + 8) * DIM + col) = make_float2(acc[mt][nt][2], acc[mt][nt][3]);
            }
        }
}

// =====================================================================
// Pass A: R[b,q,k] = 1 / sum_h exp(scale * q_h . k_h)   (fp16 MMA, LDSM)
// =====================================================================
#define ZT_W (128 * 36)
#define Z_SMEM (4 * ZT_W * 4)

__global__ __launch_bounds__(256) void attn_z() {
    extern __shared__ uint32_t smu[];
    uint32_t* sQ = smu;
    uint32_t* sK = smu + 2 * ZT_W;
    const int tid = threadIdx.x;
    const int b = blockIdx.z, qt = blockIdx.y * 128, kt = blockIdx.x * 128;
    const int w = tid >> 5, lane = tid & 31, g = lane >> 2, tg = lane & 3;
    const int wm = (w >> 2) * 64, wn = (w & 3) * 32;
    const int lrA = (lane & 7) + ((lane >> 3) & 1) * 8, lcA = (lane >> 4) * 4;
    const int lrB = (lane & 7) + (lane >> 4) * 8, lcB = ((lane >> 3) & 1) * 4;

    const __half* qb = g_q + (size_t)(b * SEQ + qt) * DIM;
    const __half* kb = g_k + (size_t)(b * SEQ + kt) * DIM;

    auto load_head = [&](int st, int h) {
        uint32_t* q = sQ + st * ZT_W;
        uint32_t* k = sK + st * ZT_W;
#pragma unroll
        for (int i = 0; i < 4; i++) {
            int c = tid + 256 * i;
            int r = c >> 3, cw = (c & 7) * 4;
            cpa16(q + r * 36 + cw, qb + (size_t)r * DIM + h * HD + cw * 2);
            cpa16(k + r * 36 + cw, kb + (size_t)r * DIM + h * HD + cw * 2);
        }
    };

    float zacc[4][4][4]{};
    load_head(0, 0);
    cp_commit();

    for (int h = 0; h < NH; h++) {
        cp_wait<0>();
        __syncthreads();
        if (h + 1 < NH) load_head((h + 1) & 1, h + 1);
        cp_commit();
        const uint32_t* q = sQ + (h & 1) * ZT_W;
        const uint32_t* k = sK + (h & 1) * ZT_W;

        float sacc[4][4][4]{};
#pragma unroll
        for (int kw = 0; kw < 32; kw += 8) {
            uint32_t af[4][4], bf[4][2];
#pragma unroll
            for (int mt = 0; mt < 4; mt++)
                ldsm4(af[mt], q + (wm + mt * 16 + lrA) * 36 + kw + lcA);
#pragma unroll
            for (int np = 0; np < 2; np++) {
                uint32_t tmp[4];
                ldsm4(tmp, k + (wn + np * 16 + lrB) * 36 + kw + lcB);
                bf[2 * np][0] = tmp[0];
                bf[2 * np][1] = tmp[1];
                bf[2 * np + 1][0] = tmp[2];
                bf[2 * np + 1][1] = tmp[3];
            }
#pragma unroll
            for (int mt = 0; mt < 4; mt++)
#pragma unroll
                for (int nt = 0; nt < 4; nt++) mma16(sacc[mt][nt], af[mt], bf[nt]);
        }
#pragma unroll
        for (int i = 0; i < 4; i++)
#pragma unroll
            for (int j = 0; j < 4; j++)
#pragma unroll
                for (int e = 0; e < 4; e++) zacc[i][j][e] += __expf(sacc[i][j][e] * SCALE);
    }
#pragma unroll
    for (int mt = 0; mt < 4; mt++)
#pragma unroll
        for (int nt = 0; nt < 4; nt++) {
            int row = qt + wm + mt * 16 + g;
            int col = kt + wn + nt * 8 + 2 * tg;
            __half* rp = g_r + ((size_t)b * SEQ + row) * SEQ + col;
            *(uint32_t*)rp = h2u(1.f / zacc[mt][nt][0], 1.f / zacc[mt][nt][1]);
            *(uint32_t*)(rp + (size_t)8 * SEQ) = h2u(1.f / zacc[mt][nt][2], 1.f / zacc[mt][nt][3]);
        }
}

// =====================================================================
// Pass B: ctx = sum_k exp(scale*S)*R * V  per (b,h,qtile)  (fp16, LDSM)
// =====================================================================
#define CQ_W (128 * 36)
#define CVT_W (64 * 68)
#define CP_W (128 * 68)
#define CR_W (128 * 68)   // fp16 R tile: 128 x 136 halves = 128*68 words
#define C_SMEM ((3 * CQ_W + CVT_W + CP_W + CR_W) * 4)

__global__ __launch_bounds__(256) void attn_ctx() {
    extern __shared__ uint32_t smu[];
    uint32_t* sQ = smu;
    uint32_t* sK = smu + CQ_W;  // [2]
    uint32_t* sVT = smu + 3 * CQ_W;
    uint32_t* sP = sVT + CVT_W;
    __half* sRh = (__half*)(sP + CP_W);  // [128][136] halves
    float* sRf = (float*)sRh;            // reduction staging [128][68] words

    const int tid = threadIdx.x;
    const int b = blockIdx.z, h = blockIdx.y, qt = blockIdx.x * 128;
    const int w = tid >> 5, lane = tid & 31, g = lane >> 2, tg = lane & 3;
    const int wm = (w >> 2) * 64, wn = (w & 3) * 32;
    const int wk2 = (w >> 1) & 1, wn2 = (w & 1) * 32;
    const int lrA = (lane & 7) + ((lane >> 3) & 1) * 8, lcA = (lane >> 4) * 4;
    const int lrB = (lane & 7) + (lane >> 4) * 8, lcB = ((lane >> 3) & 1) * 4;

    const __half* qb = g_q + (size_t)(b * SEQ + qt) * DIM + h * HD;
#pragma unroll
    for (int i = 0; i < 4; i++) {
        int c = tid + 256 * i;
        int r = c >> 3, cw = (c & 7) * 4;
        cpa16(sQ + r * 36 + cw, qb + (size_t)r * DIM + cw * 2);
    }
    {
        const __half* kb = g_k + (size_t)(b * SEQ) * DIM + h * HD;
#pragma unroll
        for (int i = 0; i < 4; i++) {
            int c = tid + 256 * i;
            int r = c >> 3, cw = (c & 7) * 4;
            cpa16(sK + r * 36 + cw, kb + (size_t)r * DIM + cw * 2);
        }
    }
    cp_commit();

    float cacc[4][4][4]{};

    for (int t = 0; t < SEQ / 128; t++) {
        const int kt = t * 128;
        {
            const __half* vtb = g_vT + ((size_t)(b * NH + h) * HD) * SEQ + kt;
#pragma unroll
            for (int i = 0; i < 4; i++) {
                int c = tid + 256 * i;
                int r = c >> 4, cw = (c & 15) * 4;
                cpa16(sVT + r * 68 + cw, vtb + (size_t)r * SEQ + cw * 2);
            }
            const __half* rb = g_r + ((size_t)b * SEQ + qt) * SEQ + kt;
#pragma unroll
            for (int i = 0; i < 8; i++) {
                int c = tid + 256 * i;
                int r = c >> 4, ch = (c & 15) * 8;
                cpa16(sRh + r * 136 + ch, rb + (size_t)r * SEQ + ch);
            }
        }
        cp_commit();
        cp_wait<1>();  // K(t) (and Q) ready
        __syncthreads();

        {
            int ktn = (t + 1 < SEQ / 128) ? kt + 128 : 0;
            const __half* kb = g_k + (size_t)(b * SEQ + ktn) * DIM + h * HD;
            uint32_t* kd = sK + ((t + 1) & 1) * CQ_W;
#pragma unroll
            for (int i = 0; i < 4; i++) {
                int c = tid + 256 * i;
                int r = c >> 3, cw = (c & 7) * 4;
                cpa16(kd + r * 36 + cw, kb + (size_t)r * DIM + cw * 2);
            }
        }
        cp_commit();

        // GEMM1: S = Q @ K^T (128x128x64)
        const uint32_t* kc = sK + (t & 1) * CQ_W;
        float sacc[4][4][4]{};
#pragma unroll
        for (int kw = 0; kw < 32; kw += 8) {
            uint32_t af[4][4], bf[4][2];
#pragma unroll
            for (int mt = 0; mt < 4; mt++)
                ldsm4(af[mt], sQ + (wm + mt * 16 + lrA) * 36 + kw + lcA);
#pragma unroll
            for (int np = 0; np < 2; np++) {
                uint32_t tmp[4];
                ldsm4(tmp, kc + (wn + np * 16 + lrB) * 36 + kw + lcB);
                bf[2 * np][0] = tmp[0];
                bf[2 * np][1] = tmp[1];
                bf[2 * np + 1][0] = tmp[2];
                bf[2 * np + 1][1] = tmp[3];
            }
#pragma unroll
            for (int mt = 0; mt < 4; mt++)
#pragma unroll
                for (int nt = 0; nt < 4; nt++) mma16(sacc[mt][nt], af[mt], bf[nt]);
        }

        cp_wait<1>();  // V(t), R(t) ready
        __syncthreads();

        // P = fp16(exp(scale*S) * R) into sP
#pragma unroll
        for (int mt = 0; mt < 4; mt++)
#pragma unroll
            for (int nt = 0; nt < 4; nt++) {
                int row = wm + mt * 16 + g;
                int colh = wn + nt * 8 + 2 * tg;
                __half2 r0 = *(__half2*)(sRh + row * 136 + colh);
                __half2 r1 = *(__half2*)(sRh + (row + 8) * 136 + colh);
                float2 rf0 = __half22float2(r0), rf1 = __half22float2(r1);
                sP[row * 68 + (colh >> 1)] =
                    h2u(__expf(sacc[mt][nt][0] * SCALE) * rf0.x, __expf(sacc[mt][nt][1] * SCALE) * rf0.y);
                sP[(row + 8) * 68 + (colh >> 1)] =
                    h2u(__expf(sacc[mt][nt][2] * SCALE) * rf1.x, __expf(sacc[mt][nt][3] * SCALE) * rf1.y);
            }
        __syncthreads();

        // GEMM2: ctx += P @ V (128x64x128, k-split over warps)
#pragma unroll
        for (int kw = 0; kw < 32; kw += 8) {
            const int kx = wk2 * 32 + kw;
            uint32_t af[4][4], bf[4][2];
#pragma unroll
            for (int mt = 0; mt < 4; mt++)
                ldsm4(af[mt], sP + (wm + mt * 16 + lrA) * 68 + kx + lcA);
#pragma unroll
            for (int np = 0; np < 2; np++) {
                uint32_t tmp[4];
                ldsm4(tmp, sVT + (wn2 + np * 16 + lrB) * 68 + kx + lcB);
                bf[2 * np][0] = tmp[0];
                bf[2 * np][1] = tmp[1];
                bf[2 * np + 1][0] = tmp[2];
                bf[2 * np + 1][1] = tmp[3];
            }
#pragma unroll
            for (int mt = 0; mt < 4; mt++)
#pragma unroll
                for (int nt = 0; nt < 4; nt++) mma16(cacc[mt][nt], af[mt], bf[nt]);
        }
        __syncthreads();
    }

    // reduce k-split partials via sRf (R tile buffer, free now)
    if (wk2 == 1) {
#pragma unroll
        for (int mt = 0; mt < 4; mt++)
#pragma unroll
            for (int nt = 0; nt < 4; nt++) {
                int row = wm + mt * 16 + g;
                int col = wn2 + nt * 8 + 2 * tg;
                *(float2*)&sRf[row * 68 + col] = make_float2(cacc[mt][nt][0], cacc[mt][nt][1]);
                *(float2*)&sRf[(row + 8) * 68 + col] = make_float2(cacc[mt][nt][2], cacc[mt][nt][3]);
            }
    }
    __syncthreads();
    if (wk2 == 0) {
        __half* cb = g_ctx + (size_t)(b * SEQ + qt) * DIM + h * HD;
#pragma unroll
        for (int mt = 0; mt < 4; mt++)
#pragma unroll
            for (int nt = 0; nt < 4; nt++) {
                int row = wm + mt * 16 + g;
                int col = wn2 + nt * 8 + 2 * tg;
                float2 o0 = *(float2*)&sRf[row * 68 + col];
                float2 o1 = *(float2*)&sRf[(row + 8) * 68 + col];
                *(uint32_t*)(cb + (size_t)row * DIM + col) =
                    h2u(o0.x + cacc[mt][nt][0], o0.y + cacc[mt][nt][1]);
                *(uint32_t*)(cb + (size_t)(row + 8) * DIM + col) =
                    h2u(o1.x + cacc[mt][nt][2], o1.y + cacc[mt][nt][3]);
            }
    }
}

// =====================================================================
extern "C" void kernel_launch(void* const* d_in, const int* in_sizes, int n_in,
                              void* d_out, int out_size) {
    const float* x = (const float*)d_in[0];
    const float* wq = (const float*)d_in[1];
    const float* wk = (const float*)d_in[2];
    const float* wv = (const float*)d_in[3];
    const float* wo = (const float*)d_in[4];
    float* out = (float*)d_out;

    __half *q, *k, *v, *ctx, *xr, *wr;
    cudaGetSymbolAddress((void**)&q, g_q);
    cudaGetSymbolAddress((void**)&k, g_k);
    cudaGetSymbolAddress((void**)&v, g_v);
    cudaGetSymbolAddress((void**)&ctx, g_ctx);
    cudaGetSymbolAddress((void**)&xr, g_x);
    cudaGetSymbolAddress((void**)&wr, g_w);

    static int attr_done = 0;
    if (!attr_done) {
        cudaFuncSetAttribute(gemm_fp16, cudaFuncAttributeMaxDynamicSharedMemorySize, G_SMEM);
        cudaFuncSetAttribute(attn_z, cudaFuncAttributeMaxDynamicSharedMemorySize, Z_SMEM);
        cudaFuncSetAttribute(attn_ctx, cudaFuncAttributeMaxDynamicSharedMemorySize, C_SMEM);
        attr_done = 1;
    }

    round_x_h<<<2048, 256>>>(x);
    round_w_t<<<dim3(32, 32, 4), 256>>>(wq, wk, wv, wo);

    dim3 gg(DIM / 256, MTOT / 128);  // (4, 64)
    gemm_fp16<<<gg, 256, G_SMEM>>>(xr, wr + 0 * DIM * DIM, q, 1);
    gemm_fp16<<<gg, 256, G_SMEM>>>(xr, wr + 1 * DIM * DIM, k, 1);
    gemm_fp16<<<gg, 256, G_SMEM>>>(xr, wr + 2 * DIM * DIM, v, 1);

    transpose_v<<<dim3(SEQ / 32, DIM / 32, BATCH), 256>>>();

    attn_z<<<dim3(SEQ / 128, SEQ / 128, BATCH), 256, Z_SMEM>>>();

    attn_ctx<<<dim3(SEQ / 128, NH, BATCH), 256, C_SMEM>>>();

    gemm_fp16<<<gg, 256, G_SMEM>>>(ctx, wr + 3 * DIM * DIM, out, 0);
}